// round 13
// baseline (speedup 1.0000x reference)
#include <cuda_runtime.h>
#include <math.h>

#define MAXN 100000
#define DM 32
#define RK 16
#define PKW 16       // padded row: 16 int32 = 64 B (32 int8 mean + 16 int8 std + 16 B zero)
#define QS 32.0f     // int8 quantization scale
#define QS2INV (1.0f / (32.0f * 32.0f))
#define GRAM_BLKS 296
#define TP 132       // padded transposed tile stride (128 rows + 4)
#define EDGE_BLKS 888
#define PACK_BLKS 3125   // ceil(100000 / 32)

// Scratch (no allocations allowed). Invariant: g_deg/g_acc/g_gram/g_misc/g_done
// are ZERO at entry (zero-init at load; re-zeroed inside the pipeline each run).
__device__ int    g_deg[MAXN];
__device__ float  g_dinv[MAXN];
__device__ double g_acc[3];          // 0: sum(z_mean^2), 1: D, 2: selfloop w sum
__device__ float  g_gram[RK * RK];   // z_std^T z_std (float atomics)
__device__ float  g_misc[2];         // 0: logdet, 1: trace(Gram)
__device__ unsigned g_done;          // completion counter for last-block finalize
__device__ __align__(16) int g_pack[MAXN * PKW];  // 6.4 MB int8 rows

// ---------------------------------------------------------------------------
// Kernel 1: degree histogram only (int4-vectorized atomics).
__global__ void __launch_bounds__(256) k_deg(const int* __restrict__ ei, int E) {
    int i0 = blockIdx.x * blockDim.x + threadIdx.x;
    int n4 = E >> 2;
    int stride = gridDim.x * blockDim.x;
    for (int i = i0; i < n4; i += stride) {
        int4 v = ((const int4*)ei)[i];
        atomicAdd(&g_deg[v.x], 1);
        atomicAdd(&g_deg[v.y], 1);
        atomicAdd(&g_deg[v.z], 1);
        atomicAdd(&g_deg[v.w], 1);
    }
    if (i0 < (E & 3)) atomicAdd(&g_deg[ei[n4 * 4 + i0]], 1);
}

// ---------------------------------------------------------------------------
__device__ __forceinline__ int q8(float v) {
    int q = __float2int_rn(v * QS);
    return max(-127, min(127, q));
}
__device__ __forceinline__ int q8x4(float4 v) {
    int a = q8(v.x), b = q8(v.y), c = q8(v.z), d = q8(v.w);
    return (a & 0xFF) | ((b & 0xFF) << 8) | ((c & 0xFF) << 16) | ((d & 0xFF) << 24);
}

// Kernel 2 fused: blocks [0,PACK_BLKS) pack int8 rows (+dinv, +sum(z_mean^2),
// +g_deg reset); blocks [PACK_BLKS,..) compute Gram (independent of deg).
__global__ void __launch_bounds__(256) k_pack_gram(
    const float* __restrict__ zm, const float* __restrict__ zs, int N) {
    if (blockIdx.x < PACK_BLKS) {
        const float MS = 0.17677669529663687f;  // 1/sqrt(32)
        int sub = threadIdx.x & 7;
        int row = blockIdx.x * 32 + (threadIdx.x >> 3);

        float acc = 0.0f;
        if (row < N) {
            int d = g_deg[row];
            float di = (d > 0) ? rsqrtf((float)d) : 0.0f;
            if (sub == 0) {
                g_dinv[row] = di;
                g_deg[row] = 0;                // fold the reset in here
            }
            float ms = di * MS;
            float4 mv = ((const float4*)(zm + (size_t)row * DM))[sub];
            acc = mv.x * mv.x + mv.y * mv.y + mv.z * mv.z + mv.w * mv.w;
            float4 mq = make_float4(mv.x * ms, mv.y * ms, mv.z * ms, mv.w * ms);
            g_pack[(size_t)row * PKW + sub] = q8x4(mq);
            if (sub < 4) {
                float4 sv = ((const float4*)(zs + (size_t)row * RK))[sub];
                float4 sq = make_float4(sv.x * di, sv.y * di, sv.z * di, sv.w * di);
                g_pack[(size_t)row * PKW + 8 + sub] = q8x4(sq);
            } else {
                g_pack[(size_t)row * PKW + 8 + sub] = 0;
            }
        }
        // block reduce sumsq
        for (int o = 16; o; o >>= 1) acc += __shfl_xor_sync(0xffffffffu, acc, o);
        __shared__ float sh[8];
        int w = threadIdx.x >> 5, l = threadIdx.x & 31;
        if (l == 0) sh[w] = acc;
        __syncthreads();
        if (threadIdx.x == 0) {
            float s = 0.0f;
            for (int i = 0; i < 8; i++) s += sh[i];
            atomicAdd(&g_acc[0], (double)s);
        }
    } else {
        // ---- Gram: transposed padded tile, LDS.128 inner loop ----
        __shared__ float sh[RK * TP];          // [col][row], pad 132
        int a = threadIdx.x >> 4, b = threadIdx.x & 15;
        int gb = blockIdx.x - PACK_BLKS;
        float acc = 0.0f;
        for (int row0 = gb * 128; row0 < N; row0 += GRAM_BLKS * 128) {
            __syncthreads();
            for (int t = threadIdx.x; t < 512; t += 256) {
                int row = t >> 2;              // 0..127
                int cb = (t & 3) * 4;          // col base 0,4,8,12
                int grow = row0 + row;
                float4 v = make_float4(0.f, 0.f, 0.f, 0.f);
                if (grow < N) v = ((const float4*)zs)[(size_t)grow * 4 + (t & 3)];
                sh[(cb + 0) * TP + row] = v.x;
                sh[(cb + 1) * TP + row] = v.y;
                sh[(cb + 2) * TP + row] = v.z;
                sh[(cb + 3) * TP + row] = v.w;
            }
            __syncthreads();
            const float4* ca = (const float4*)(sh + a * TP);
            const float4* cb4 = (const float4*)(sh + b * TP);
#pragma unroll 8
            for (int i = 0; i < 32; i++) {
                float4 va = ca[i];
                float4 vb = cb4[i];
                acc += va.x * vb.x + va.y * vb.y + va.z * vb.z + va.w * vb.w;
            }
        }
        atomicAdd(&g_gram[threadIdx.x], acc);
    }
}

// ---------------------------------------------------------------------------
__device__ __forceinline__ void edge_dp(int r, int c, int sub, int& accI,
                                        float& aself) {
    int4 ua = __ldg((const int4*)(g_pack + (size_t)r * PKW) + sub);
    int4 ub = __ldg((const int4*)(g_pack + (size_t)c * PKW) + sub);
    accI = __dp4a(ua.x, ub.x, accI);
    accI = __dp4a(ua.y, ub.y, accI);
    accI = __dp4a(ua.z, ub.z, accI);
    accI = __dp4a(ua.w, ub.w, accI);
    if (sub == 3 && r == c) {
        float di = g_dinv[r];
        aself += di * di;
    }
}

// After a block's contribution is globally visible, bump the counter; the
// LAST block (of EDGE_BLKS+1) combines everything, writes out, resets state.
__device__ __forceinline__ void finalize_if_last(float* out, int N) {
    __threadfence();
    if (threadIdx.x == 0) {
        unsigned v = atomicAdd(&g_done, 1u);
        if (v == EDGE_BLKS) {                  // last of EDGE_BLKS+1 blocks
            double logdet = (double)g_misc[0];
            double tr = (double)g_misc[1];
            double trace_L = (double)N - g_acc[2];
            double res = (g_acc[0] / (double)DM + tr + trace_L - g_acc[1]
                          - logdet) / (2.0 * (double)N);
            out[0] = (float)res;
            g_acc[0] = 0.0; g_acc[1] = 0.0; g_acc[2] = 0.0;
            g_misc[0] = 0.0f; g_misc[1] = 0.0f;
            g_done = 0u;
        }
    }
}

// Kernel 3. Blocks [0,EDGE_BLKS): per-edge int8 dp4a dot (4 lanes/edge,
// 4 edges in flight). Block EDGE_BLKS: shuffle-register Cholesky of I+Gram
// (gram final since kernel 2), stores logdet+trace, re-zeros g_gram.
// Last block to finish combines and writes the result (no k_final launch).
__global__ void __launch_bounds__(256) k_edges(
    const int* __restrict__ ei, int E, float* out, int N) {
    if (blockIdx.x >= EDGE_BLKS) {
        int tid = threadIdx.x;
        if (tid < 32) {
            int i = tid;                       // lanes 16-31: inert mirrors
            float m[RK];
            float tr = 0.0f;
#pragma unroll
            for (int j = 0; j < RK; j++) {
                float g = (i < RK) ? g_gram[i * RK + j] : 0.0f;
                m[j] = g + (i == j ? 1.0f : 0.0f);
                if (i == j) tr = g;
            }
            for (int o = 8; o; o >>= 1) tr += __shfl_xor_sync(0xffffffffu, tr, o);

            // logdet = sum log(pivot d_k); rows scaled by rsqrt(d_k) (no div).
            float logdet = 0.0f;
#pragma unroll
            for (int k = 0; k < RK; k++) {
                float d = __shfl_sync(0xffffffffu, m[k], k);
                logdet += __logf(d);
                float rinv = rsqrtf(d);
                if (i >= k) m[k] *= rinv;      // column k of L
#pragma unroll
                for (int j = k + 1; j < RK; j++) {
                    float ljk = __shfl_sync(0xffffffffu, m[k], j);
                    if (i >= j) m[j] -= m[k] * ljk;
                }
            }
            if (tid == 0) {
                g_misc[0] = logdet;
                g_misc[1] = tr;
            }
        }
        __syncthreads();
        if (threadIdx.x < RK * RK) g_gram[threadIdx.x] = 0.0f;  // reset for replay
        finalize_if_last(out, N);
        return;
    }

    int tid = blockIdx.x * blockDim.x + threadIdx.x;
    int sub = threadIdx.x & 3;
    int gid = tid >> 2;
    int gstride = (EDGE_BLKS * 256) >> 2;

    int acc0 = 0, acc1 = 0, acc2 = 0, acc3 = 0;
    float aself = 0.0f;

    int iters = (E + gstride - 1) / gstride;
    int U = iters - 1;                 // unguarded iterations
    int it = 0;
    for (; it + 3 < U; it += 4) {
        int e0 = gid + it * gstride;
        int e1 = e0 + gstride, e2 = e1 + gstride, e3 = e2 + gstride;
        int r0 = __ldg(ei + e0), c0 = __ldg(ei + (size_t)E + e0);
        int r1 = __ldg(ei + e1), c1 = __ldg(ei + (size_t)E + e1);
        int r2 = __ldg(ei + e2), c2 = __ldg(ei + (size_t)E + e2);
        int r3 = __ldg(ei + e3), c3 = __ldg(ei + (size_t)E + e3);
        edge_dp(r0, c0, sub, acc0, aself);
        edge_dp(r1, c1, sub, acc1, aself);
        edge_dp(r2, c2, sub, acc2, aself);
        edge_dp(r3, c3, sub, acc3, aself);
    }
    for (; it < U; it++) {
        int e = gid + it * gstride;
        int r = __ldg(ei + e), c = __ldg(ei + (size_t)E + e);
        edge_dp(r, c, sub, acc0, aself);
    }
    {                                  // guarded tail
        int e = gid + U * gstride;
        if (e < E) {
            int r = __ldg(ei + e), c = __ldg(ei + (size_t)E + e);
            edge_dp(r, c, sub, acc1, aself);
        }
    }

    float accD = (float)((acc0 + acc1) + (acc2 + acc3)) * QS2INV;

    // block reduce
    for (int o = 16; o; o >>= 1) {
        accD += __shfl_xor_sync(0xffffffffu, accD, o);
        aself += __shfl_xor_sync(0xffffffffu, aself, o);
    }
    __shared__ float s0[8], s1[8];
    int w = threadIdx.x >> 5, l = threadIdx.x & 31;
    if (l == 0) { s0[w] = accD; s1[w] = aself; }
    __syncthreads();
    if (threadIdx.x == 0) {
        float A = 0.f, B = 0.f;
        for (int i = 0; i < 8; i++) { A += s0[i]; B += s1[i]; }
        atomicAdd(&g_acc[1], (double)A);
        atomicAdd(&g_acc[2], (double)B);
    }
    finalize_if_last(out, N);
}

// ---------------------------------------------------------------------------
extern "C" void kernel_launch(void* const* d_in, const int* in_sizes, int n_in,
                              void* d_out, int out_size) {
    const float* zm = (const float*)d_in[0];
    const float* zs = (const float*)d_in[1];
    const int*   ei = (const int*)d_in[2];

    int N = in_sizes[0] / DM;
    int E = in_sizes[2] / 2;

    k_deg<<<1184, 256>>>(ei, E);
    k_pack_gram<<<PACK_BLKS + GRAM_BLKS, 256>>>(zm, zs, N);
    k_edges<<<EDGE_BLKS + 1, 256>>>(ei, E, (float*)d_out, N);
}

// round 14
// speedup vs baseline: 1.5367x; 1.5367x over previous
#include <cuda_runtime.h>
#include <math.h>

#define MAXN 100000
#define DM 32
#define RK 16
#define PKW 16       // padded row: 16 int32 = 64 B (32 int8 mean + 16 int8 std + 16 B zero)
#define QS 32.0f     // int8 quantization scale
#define QS2INV (1.0f / (32.0f * 32.0f))
#define GRAM_BLKS 296
#define TP 132       // padded transposed tile stride (128 rows + 4)
#define EDGE_BLKS 888

// Scratch (no allocations allowed). Invariant: g_deg/g_acc/g_gram/g_misc/g_done
// are ZERO at entry (zero-init at load; re-zeroed inside the pipeline each run).
__device__ int    g_deg[MAXN];
__device__ float  g_dinv[MAXN];
__device__ double g_acc[3];          // 0: sum(z_mean^2), 1: D, 2: selfloop w sum
__device__ float  g_gram[RK * RK];   // z_std^T z_std (float atomics)
__device__ float  g_misc[2];         // 0: logdet, 1: trace(Gram)
__device__ unsigned g_done;          // completion counter for last-block finalize
__device__ __align__(16) int g_pack[MAXN * PKW];  // 6.4 MB int8 rows

// ---------------------------------------------------------------------------
// Kernel 1 fused: blocks [0,GRAM_BLKS) compute Gram = z_std^T z_std;
//        blocks [GRAM_BLKS,..) compute the degree histogram (independent work,
//        overlaps the gram blocks' shared-memory work with L2 atomics).
__global__ void __launch_bounds__(256) k_deg_gram(
    const float* __restrict__ zs, const int* __restrict__ ei, int N, int E) {
    if (blockIdx.x < GRAM_BLKS) {
        // ---- Gram part: transposed padded tile, LDS.128 inner loop ----
        __shared__ float sh[RK * TP];          // [col][row], pad 132
        int a = threadIdx.x >> 4, b = threadIdx.x & 15;
        float acc = 0.0f;
        for (int row0 = blockIdx.x * 128; row0 < N; row0 += GRAM_BLKS * 128) {
            __syncthreads();
            for (int t = threadIdx.x; t < 512; t += 256) {
                int row = t >> 2;              // 0..127
                int cb = (t & 3) * 4;          // col base 0,4,8,12
                int grow = row0 + row;
                float4 v = make_float4(0.f, 0.f, 0.f, 0.f);
                if (grow < N) v = ((const float4*)zs)[(size_t)grow * 4 + (t & 3)];
                sh[(cb + 0) * TP + row] = v.x;
                sh[(cb + 1) * TP + row] = v.y;
                sh[(cb + 2) * TP + row] = v.z;
                sh[(cb + 3) * TP + row] = v.w;
            }
            __syncthreads();
            const float4* ca = (const float4*)(sh + a * TP);
            const float4* cb4 = (const float4*)(sh + b * TP);
#pragma unroll 8
            for (int i = 0; i < 32; i++) {
                float4 va = ca[i];
                float4 vb = cb4[i];
                acc += va.x * vb.x + va.y * vb.y + va.z * vb.z + va.w * vb.w;
            }
        }
        atomicAdd(&g_gram[threadIdx.x], acc);
    } else {
        // ---- degree histogram part (int4-vectorized) ----
        int nb = gridDim.x - GRAM_BLKS;
        int i0 = (blockIdx.x - GRAM_BLKS) * blockDim.x + threadIdx.x;
        int n4 = E >> 2;
        for (int i = i0; i < n4; i += nb * blockDim.x) {
            int4 v = ((const int4*)ei)[i];
            atomicAdd(&g_deg[v.x], 1);
            atomicAdd(&g_deg[v.y], 1);
            atomicAdd(&g_deg[v.z], 1);
            atomicAdd(&g_deg[v.w], 1);
        }
        if (i0 < (E & 3)) atomicAdd(&g_deg[ei[n4 * 4 + i0]], 1);
    }
}

// ---------------------------------------------------------------------------
__device__ __forceinline__ int q8(float v) {
    int q = __float2int_rn(v * QS);
    return max(-127, min(127, q));
}
__device__ __forceinline__ int q8x4(float4 v) {
    int a = q8(v.x), b = q8(v.y), c = q8(v.z), d = q8(v.w);
    return (a & 0xFF) | ((b & 0xFF) << 8) | ((c & 0xFF) << 16) | ((d & 0xFF) << 24);
}

// Pack per-node scaled rows to int8 (64B padded); fuse dinv + sum(z_mean^2).
// Also RE-ZEROS g_deg (each row's owner, right after the read).
__global__ void __launch_bounds__(256) k_pack(
    const float* __restrict__ zm, const float* __restrict__ zs, int N) {
    const float MS = 0.17677669529663687f;  // 1/sqrt(32)
    int sub = threadIdx.x & 7;
    int row = blockIdx.x * 32 + (threadIdx.x >> 3);

    float acc = 0.0f;
    if (row < N) {
        int d = g_deg[row];
        float di = (d > 0) ? rsqrtf((float)d) : 0.0f;
        if (sub == 0) {
            g_dinv[row] = di;
            g_deg[row] = 0;                    // fold the reset in here
        }
        float ms = di * MS;
        float4 mv = ((const float4*)(zm + (size_t)row * DM))[sub];
        acc = mv.x * mv.x + mv.y * mv.y + mv.z * mv.z + mv.w * mv.w;
        float4 mq = make_float4(mv.x * ms, mv.y * ms, mv.z * ms, mv.w * ms);
        g_pack[(size_t)row * PKW + sub] = q8x4(mq);
        if (sub < 4) {
            float4 sv = ((const float4*)(zs + (size_t)row * RK))[sub];
            float4 sq = make_float4(sv.x * di, sv.y * di, sv.z * di, sv.w * di);
            g_pack[(size_t)row * PKW + 8 + sub] = q8x4(sq);
        } else {
            g_pack[(size_t)row * PKW + 8 + sub] = 0;
        }
    }
    // block reduce sumsq
    for (int o = 16; o; o >>= 1) acc += __shfl_xor_sync(0xffffffffu, acc, o);
    __shared__ float sh[8];
    int w = threadIdx.x >> 5, l = threadIdx.x & 31;
    if (l == 0) sh[w] = acc;
    __syncthreads();
    if (threadIdx.x == 0) {
        float s = 0.0f;
        for (int i = 0; i < 8; i++) s += sh[i];
        atomicAdd(&g_acc[0], (double)s);
    }
}

// ---------------------------------------------------------------------------
__device__ __forceinline__ void edge_dp(int r, int c, int sub, int& accI,
                                        float& aself) {
    int4 ua = __ldg((const int4*)(g_pack + (size_t)r * PKW) + sub);
    int4 ub = __ldg((const int4*)(g_pack + (size_t)c * PKW) + sub);
    accI = __dp4a(ua.x, ub.x, accI);
    accI = __dp4a(ua.y, ub.y, accI);
    accI = __dp4a(ua.z, ub.z, accI);
    accI = __dp4a(ua.w, ub.w, accI);
    if (sub == 3 && r == c) {
        float di = g_dinv[r];
        aself += di * di;
    }
}

// After a block's contribution is globally visible, bump the counter; the
// LAST block (of EDGE_BLKS+1) combines everything, writes out, resets state.
__device__ __forceinline__ void finalize_if_last(float* out, int N) {
    __threadfence();
    if (threadIdx.x == 0) {
        unsigned v = atomicAdd(&g_done, 1u);
        if (v == EDGE_BLKS) {                  // last of EDGE_BLKS+1 blocks
            double logdet = (double)g_misc[0];
            double tr = (double)g_misc[1];
            double trace_L = (double)N - g_acc[2];
            double res = (g_acc[0] / (double)DM + tr + trace_L - g_acc[1]
                          - logdet) / (2.0 * (double)N);
            out[0] = (float)res;
            g_acc[0] = 0.0; g_acc[1] = 0.0; g_acc[2] = 0.0;
            g_misc[0] = 0.0f; g_misc[1] = 0.0f;
            g_done = 0u;
        }
    }
}

// Kernel 3. Blocks [0,EDGE_BLKS): per-edge int8 dp4a dot (4 lanes/edge,
// 4 edges in flight). Block EDGE_BLKS: shuffle-register Cholesky of I+Gram
// (gram final since kernel 1), stores logdet+trace, re-zeros g_gram.
// Last block to finish combines and writes the result (no k_final launch).
__global__ void __launch_bounds__(256) k_edges(
    const int* __restrict__ ei, int E, float* out, int N) {
    if (blockIdx.x >= EDGE_BLKS) {
        int tid = threadIdx.x;
        if (tid < 32) {
            int i = tid;                       // lanes 16-31: inert mirrors
            float m[RK];
            float tr = 0.0f;
#pragma unroll
            for (int j = 0; j < RK; j++) {
                float g = (i < RK) ? g_gram[i * RK + j] : 0.0f;
                m[j] = g + (i == j ? 1.0f : 0.0f);
                if (i == j) tr = g;
            }
            for (int o = 8; o; o >>= 1) tr += __shfl_xor_sync(0xffffffffu, tr, o);

            // logdet = sum log(pivot d_k); rows scaled by rsqrt(d_k) (no div).
            float logdet = 0.0f;
#pragma unroll
            for (int k = 0; k < RK; k++) {
                float d = __shfl_sync(0xffffffffu, m[k], k);
                logdet += __logf(d);
                float rinv = rsqrtf(d);
                if (i >= k) m[k] *= rinv;      // column k of L
#pragma unroll
                for (int j = k + 1; j < RK; j++) {
                    float ljk = __shfl_sync(0xffffffffu, m[k], j);
                    if (i >= j) m[j] -= m[k] * ljk;
                }
            }
            if (tid == 0) {
                g_misc[0] = logdet;
                g_misc[1] = tr;
            }
        }
        __syncthreads();
        if (threadIdx.x < RK * RK) g_gram[threadIdx.x] = 0.0f;  // reset for replay
        finalize_if_last(out, N);
        return;
    }

    int tid = blockIdx.x * blockDim.x + threadIdx.x;
    int sub = threadIdx.x & 3;
    int gid = tid >> 2;
    int gstride = (EDGE_BLKS * 256) >> 2;

    int acc0 = 0, acc1 = 0, acc2 = 0, acc3 = 0;
    float aself = 0.0f;

    int iters = (E + gstride - 1) / gstride;
    int U = iters - 1;                 // unguarded iterations
    int it = 0;
    for (; it + 3 < U; it += 4) {
        int e0 = gid + it * gstride;
        int e1 = e0 + gstride, e2 = e1 + gstride, e3 = e2 + gstride;
        int r0 = __ldg(ei + e0), c0 = __ldg(ei + (size_t)E + e0);
        int r1 = __ldg(ei + e1), c1 = __ldg(ei + (size_t)E + e1);
        int r2 = __ldg(ei + e2), c2 = __ldg(ei + (size_t)E + e2);
        int r3 = __ldg(ei + e3), c3 = __ldg(ei + (size_t)E + e3);
        edge_dp(r0, c0, sub, acc0, aself);
        edge_dp(r1, c1, sub, acc1, aself);
        edge_dp(r2, c2, sub, acc2, aself);
        edge_dp(r3, c3, sub, acc3, aself);
    }
    for (; it < U; it++) {
        int e = gid + it * gstride;
        int r = __ldg(ei + e), c = __ldg(ei + (size_t)E + e);
        edge_dp(r, c, sub, acc0, aself);
    }
    {                                  // guarded tail
        int e = gid + U * gstride;
        if (e < E) {
            int r = __ldg(ei + e), c = __ldg(ei + (size_t)E + e);
            edge_dp(r, c, sub, acc1, aself);
        }
    }

    float accD = (float)((acc0 + acc1) + (acc2 + acc3)) * QS2INV;

    // block reduce
    for (int o = 16; o; o >>= 1) {
        accD += __shfl_xor_sync(0xffffffffu, accD, o);
        aself += __shfl_xor_sync(0xffffffffu, aself, o);
    }
    __shared__ float s0[8], s1[8];
    int w = threadIdx.x >> 5, l = threadIdx.x & 31;
    if (l == 0) { s0[w] = accD; s1[w] = aself; }
    __syncthreads();
    if (threadIdx.x == 0) {
        float A = 0.f, B = 0.f;
        for (int i = 0; i < 8; i++) { A += s0[i]; B += s1[i]; }
        atomicAdd(&g_acc[1], (double)A);
        atomicAdd(&g_acc[2], (double)B);
    }
    finalize_if_last(out, N);
}

// ---------------------------------------------------------------------------
extern "C" void kernel_launch(void* const* d_in, const int* in_sizes, int n_in,
                              void* d_out, int out_size) {
    const float* zm = (const float*)d_in[0];
    const float* zs = (const float*)d_in[1];
    const int*   ei = (const int*)d_in[2];

    int N = in_sizes[0] / DM;
    int E = in_sizes[2] / 2;

    k_deg_gram<<<GRAM_BLKS + 1264, 256>>>(zs, ei, N, E);
    k_pack<<<(N + 31) / 32, 256>>>(zm, zs, N);
    k_edges<<<EDGE_BLKS + 1, 256>>>(ei, E, (float*)d_out, N);
}

// round 15
// speedup vs baseline: 1.6126x; 1.0494x over previous
#include <cuda_runtime.h>
#include <math.h>

#define MAXN 100000
#define DM 32
#define RK 16
#define PKW 16        // row: 16 int32 = 64 B (32 int8 mean, 16 int8 std, word12 = di, 3 zero words)
#define QSM 128.0f    // mean quant scale (applied to zm/sqrt(32))
#define QSS 24.0f     // std quant scale (applied to zs)
#define CM  (1.0f / (128.0f * 128.0f))
#define CS  (1.0f / (24.0f * 24.0f))
#define DEG_BLKS 592
#define GRAM_BLKS 296
#define PACK_BLKS 3125
#define TP 132        // padded transposed tile stride
#define EDGE_BLKS 888

// Scratch. Invariant: g_deg/g_acc/g_gram/g_misc/g_done are ZERO at entry
// (zero-init at load; re-zeroed inside the pipeline every run).
__device__ int    g_deg[MAXN];
__device__ double g_acc[3];          // 0: sum(z_mean^2), 1: D, 2: selfloop w sum
__device__ float  g_gram[RK * RK];   // z_std^T z_std (float atomics)
__device__ float  g_misc[2];         // 0: logdet, 1: trace(Gram)
__device__ unsigned g_done;          // completion counter for last-block finalize
__device__ __align__(16) int g_pack[MAXN * PKW];  // 6.4 MB rows

// ---------------------------------------------------------------------------
__device__ __forceinline__ int q8(float v) {
    int q = __float2int_rn(v);
    return max(-127, min(127, q));
}
__device__ __forceinline__ int q8x4(float4 v, float s) {
    int a = q8(v.x * s), b = q8(v.y * s), c = q8(v.z * s), d = q8(v.w * s);
    return (a & 0xFF) | ((b & 0xFF) << 8) | ((c & 0xFF) << 16) | ((d & 0xFF) << 24);
}

// Kernel 1: three independent jobs in one launch (deg ∥ gram ∥ pack).
__global__ void __launch_bounds__(256) k_prep(
    const float* __restrict__ zm, const float* __restrict__ zs,
    const int* __restrict__ ei, int N, int E) {
    if (blockIdx.x < DEG_BLKS) {
        // ---- degree histogram (int4-vectorized atomics) ----
        int i0 = blockIdx.x * blockDim.x + threadIdx.x;
        int n4 = E >> 2;
        for (int i = i0; i < n4; i += DEG_BLKS * 256) {
            int4 v = ((const int4*)ei)[i];
            atomicAdd(&g_deg[v.x], 1);
            atomicAdd(&g_deg[v.y], 1);
            atomicAdd(&g_deg[v.z], 1);
            atomicAdd(&g_deg[v.w], 1);
        }
        if (i0 < (E & 3)) atomicAdd(&g_deg[ei[n4 * 4 + i0]], 1);
    } else if (blockIdx.x < DEG_BLKS + GRAM_BLKS) {
        // ---- Gram: transposed padded tile, LDS.128 inner loop ----
        __shared__ float sh[RK * TP];
        int a = threadIdx.x >> 4, b = threadIdx.x & 15;
        int gb = blockIdx.x - DEG_BLKS;
        float acc = 0.0f;
        for (int row0 = gb * 128; row0 < N; row0 += GRAM_BLKS * 128) {
            __syncthreads();
            for (int t = threadIdx.x; t < 512; t += 256) {
                int row = t >> 2;
                int cb = (t & 3) * 4;
                int grow = row0 + row;
                float4 v = make_float4(0.f, 0.f, 0.f, 0.f);
                if (grow < N) v = ((const float4*)zs)[(size_t)grow * 4 + (t & 3)];
                sh[(cb + 0) * TP + row] = v.x;
                sh[(cb + 1) * TP + row] = v.y;
                sh[(cb + 2) * TP + row] = v.z;
                sh[(cb + 3) * TP + row] = v.w;
            }
            __syncthreads();
            const float4* ca = (const float4*)(sh + a * TP);
            const float4* cb4 = (const float4*)(sh + b * TP);
#pragma unroll 8
            for (int i = 0; i < 32; i++) {
                float4 va = ca[i];
                float4 vb = cb4[i];
                acc += va.x * vb.x + va.y * vb.y + va.z * vb.z + va.w * vb.w;
            }
        }
        atomicAdd(&g_gram[threadIdx.x], acc);
    } else {
        // ---- pack UNSCALED int8 rows (no deg dependency) + sum(z_mean^2) ----
        const float MSQ = 0.17677669529663687f * QSM;  // (1/sqrt(32)) * QSM
        int sub = threadIdx.x & 7;
        int row = (blockIdx.x - DEG_BLKS - GRAM_BLKS) * 32 + (threadIdx.x >> 3);

        float acc = 0.0f;
        if (row < N) {
            float4 mv = ((const float4*)(zm + (size_t)row * DM))[sub];
            acc = mv.x * mv.x + mv.y * mv.y + mv.z * mv.z + mv.w * mv.w;
            g_pack[(size_t)row * PKW + sub] = q8x4(mv, MSQ);
            if (sub < 4) {
                float4 sv = ((const float4*)(zs + (size_t)row * RK))[sub];
                g_pack[(size_t)row * PKW + 8 + sub] = q8x4(sv, QSS);
            } else {
                g_pack[(size_t)row * PKW + 8 + sub] = 0;  // words 12-15 (12 patched later)
            }
        }
        for (int o = 16; o; o >>= 1) acc += __shfl_xor_sync(0xffffffffu, acc, o);
        __shared__ float sh[8];
        int w = threadIdx.x >> 5, l = threadIdx.x & 31;
        if (l == 0) sh[w] = acc;
        __syncthreads();
        if (threadIdx.x == 0) {
            float s = 0.0f;
            for (int i = 0; i < 8; i++) s += sh[i];
            atomicAdd(&g_acc[0], (double)s);
        }
    }
}

// Kernel 2: block 0 = shuffle-register Cholesky of I+Gram (then zero g_gram);
// blocks 1..: di = rsqrt(deg) written into row padding word 12, zero g_deg.
__global__ void __launch_bounds__(256) k_patch(int N) {
    if (blockIdx.x == 0) {
        int tid = threadIdx.x;
        if (tid < 32) {
            int i = tid;                       // lanes 16-31: inert mirrors
            float m[RK];
            float tr = 0.0f;
#pragma unroll
            for (int j = 0; j < RK; j++) {
                float g = (i < RK) ? g_gram[i * RK + j] : 0.0f;
                m[j] = g + (i == j ? 1.0f : 0.0f);
                if (i == j) tr = g;
            }
            for (int o = 8; o; o >>= 1) tr += __shfl_xor_sync(0xffffffffu, tr, o);

            float logdet = 0.0f;
#pragma unroll
            for (int k = 0; k < RK; k++) {
                float d = __shfl_sync(0xffffffffu, m[k], k);
                logdet += __logf(d);
                float rinv = rsqrtf(d);
                if (i >= k) m[k] *= rinv;
#pragma unroll
                for (int j = k + 1; j < RK; j++) {
                    float ljk = __shfl_sync(0xffffffffu, m[k], j);
                    if (i >= j) m[j] -= m[k] * ljk;
                }
            }
            if (tid == 0) {
                g_misc[0] = logdet;
                g_misc[1] = tr;
            }
        }
        __syncthreads();
        if (threadIdx.x < RK * RK) g_gram[threadIdx.x] = 0.0f;
    } else {
        int node = (blockIdx.x - 1) * 256 + threadIdx.x;
        if (node < N) {
            int d = g_deg[node];
            float di = (d > 0) ? rsqrtf((float)d) : 0.0f;
            ((float*)g_pack)[(size_t)node * PKW + 12] = di;
            g_deg[node] = 0;                   // reset for next replay
        }
    }
}

// ---------------------------------------------------------------------------
// Last block (of EDGE_BLKS) combines everything, writes out, resets state.
__device__ __forceinline__ void finalize_if_last(float* out, int N) {
    __threadfence();
    if (threadIdx.x == 0) {
        unsigned v = atomicAdd(&g_done, 1u);
        if (v == EDGE_BLKS - 1) {
            double logdet = (double)g_misc[0];
            double tr = (double)g_misc[1];
            double trace_L = (double)N - g_acc[2];
            double res = (g_acc[0] / (double)DM + tr + trace_L - g_acc[1]
                          - logdet) / (2.0 * (double)N);
            out[0] = (float)res;
            g_acc[0] = 0.0; g_acc[1] = 0.0; g_acc[2] = 0.0;
            g_misc[0] = 0.0f; g_misc[1] = 0.0f;
            g_done = 0u;
        }
    }
}

// Per-edge body: 4 lanes/edge. Lanes 0-2 dp4a their 16B chunk; lane 3's chunk
// carries di in word 12 -> computes w = di_r*di_c, broadcast by shfl to the
// group; each lane accumulates w * (float)partial. Per-lane scale applied once
// at the end (lane 3's garbage partial gets scale 0). No extra wavefronts.
__device__ __forceinline__ void edge_body(int r, int c, int sub, int lane,
                                          float& accF, float& aself) {
    int4 ua = __ldg((const int4*)(g_pack + (size_t)r * PKW) + sub);
    int4 ub = __ldg((const int4*)(g_pack + (size_t)c * PKW) + sub);
    float fw = 0.0f;
    if (sub == 3) {
        float dr = __int_as_float(ua.x);
        float dc = __int_as_float(ub.x);
        fw = dr * dc;
        if (r == c) aself += dr * dr;
    }
    int p = 0;
    p = __dp4a(ua.x, ub.x, p);
    p = __dp4a(ua.y, ub.y, p);
    p = __dp4a(ua.z, ub.z, p);
    p = __dp4a(ua.w, ub.w, p);
    fw = __shfl_sync(0xffffffffu, fw, lane | 3);
    accF = fmaf(fw, (float)p, accF);
}

// Kernel 3: edges (EDGE_BLKS blocks) + last-block finalize.
__global__ void __launch_bounds__(256) k_edges(
    const int* __restrict__ ei, int E, float* out, int N) {
    int tid = blockIdx.x * blockDim.x + threadIdx.x;
    int sub = threadIdx.x & 3;
    int lane = threadIdx.x & 31;
    int gid = tid >> 2;
    int gstride = (EDGE_BLKS * 256) >> 2;

    float acc0 = 0.f, acc1 = 0.f, acc2 = 0.f, acc3 = 0.f;
    float aself = 0.0f;

    int iters = (E + gstride - 1) / gstride;
    int U = iters - 1;                 // unguarded iterations
    int it = 0;
    for (; it + 3 < U; it += 4) {
        int e0 = gid + it * gstride;
        int e1 = e0 + gstride, e2 = e1 + gstride, e3 = e2 + gstride;
        int r0 = __ldg(ei + e0), c0 = __ldg(ei + (size_t)E + e0);
        int r1 = __ldg(ei + e1), c1 = __ldg(ei + (size_t)E + e1);
        int r2 = __ldg(ei + e2), c2 = __ldg(ei + (size_t)E + e2);
        int r3 = __ldg(ei + e3), c3 = __ldg(ei + (size_t)E + e3);
        edge_body(r0, c0, sub, lane, acc0, aself);
        edge_body(r1, c1, sub, lane, acc1, aself);
        edge_body(r2, c2, sub, lane, acc2, aself);
        edge_body(r3, c3, sub, lane, acc3, aself);
    }
    for (; it < U; it++) {
        int e = gid + it * gstride;
        int r = __ldg(ei + e), c = __ldg(ei + (size_t)E + e);
        edge_body(r, c, sub, lane, acc0, aself);
    }
    {                                  // guarded tail
        int e = gid + U * gstride;
        if (e < E) {
            int r = __ldg(ei + e), c = __ldg(ei + (size_t)E + e);
            edge_body(r, c, sub, lane, acc1, aself);
        }
    }

    // per-lane scale: lanes 0,1 mean (CM), lane 2 std (CS), lane 3 excluded
    float lscale = (sub < 2) ? CM : ((sub == 2) ? CS : 0.0f);
    float accD = ((acc0 + acc1) + (acc2 + acc3)) * lscale;

    // block reduce
    for (int o = 16; o; o >>= 1) {
        accD += __shfl_xor_sync(0xffffffffu, accD, o);
        aself += __shfl_xor_sync(0xffffffffu, aself, o);
    }
    __shared__ float s0[8], s1[8];
    int w = threadIdx.x >> 5, l = threadIdx.x & 31;
    if (l == 0) { s0[w] = accD; s1[w] = aself; }
    __syncthreads();
    if (threadIdx.x == 0) {
        float A = 0.f, B = 0.f;
        for (int i = 0; i < 8; i++) { A += s0[i]; B += s1[i]; }
        atomicAdd(&g_acc[1], (double)A);
        atomicAdd(&g_acc[2], (double)B);
    }
    finalize_if_last(out, N);
}

// ---------------------------------------------------------------------------
extern "C" void kernel_launch(void* const* d_in, const int* in_sizes, int n_in,
                              void* d_out, int out_size) {
    const float* zm = (const float*)d_in[0];
    const float* zs = (const float*)d_in[1];
    const int*   ei = (const int*)d_in[2];

    int N = in_sizes[0] / DM;
    int E = in_sizes[2] / 2;

    k_prep<<<DEG_BLKS + GRAM_BLKS + PACK_BLKS, 256>>>(zm, zs, ei, N, E);
    k_patch<<<1 + (N + 255) / 256, 256>>>(N);
    k_edges<<<EDGE_BLKS, 256>>>(ei, E, (float*)d_out, N);
}

// round 16
// speedup vs baseline: 1.7524x; 1.0867x over previous
#include <cuda_runtime.h>
#include <math.h>

#define MAXN 100000
#define DM 32
#define RK 16
#define PKW 8          // row: 8 int32 = 32 B (4w mean nib, 2w std nib, 1w di, 1w sums)
#define QS4M 11.0f     // int4 mean quant scale (applied to zm/sqrt(32))
#define QS4S 2.0f      // int4 std quant scale
#define MSQ4 (0.17677669529663687f * QS4M)
#define CM4  (1.0f / (QS4M * QS4M))
#define CS4  (1.0f / (QS4S * QS4S))
#define DEG_BLKS 592
#define GRAM_BLKS 296
#define PACK_BLKS 3125
#define TP 132         // padded transposed tile stride
#define EDGE_BLKS 888

// Scratch. Invariant: g_deg/g_acc/g_gram/g_misc/g_done are ZERO at entry
// (zero-init at load; re-zeroed inside the pipeline every run).
__device__ int    g_deg[MAXN];
__device__ double g_acc[3];          // 0: sum(z_mean^2), 1: D, 2: selfloop w sum
__device__ float  g_gram[RK * RK];   // z_std^T z_std (float atomics)
__device__ float  g_misc[2];         // 0: logdet, 1: trace(Gram)
__device__ unsigned g_done;          // completion counter for last-block finalize
__device__ __align__(32) int g_pack[MAXN * PKW];  // 3.2 MB nibble rows

// ---------------------------------------------------------------------------
__device__ __forceinline__ int q4n(float v, float s) {   // biased nibble 1..15
    int q = __float2int_rn(v * s);
    return max(-7, min(7, q)) + 8;
}

// Kernel 1: three independent jobs in one launch (deg ∥ gram ∥ pack).
__global__ void __launch_bounds__(256) k_prep(
    const float* __restrict__ zm, const float* __restrict__ zs,
    const int* __restrict__ ei, int N, int E) {
    if (blockIdx.x < DEG_BLKS) {
        // ---- degree histogram (int4-vectorized atomics over row half) ----
        int i0 = blockIdx.x * blockDim.x + threadIdx.x;
        int n4 = E >> 2;
        for (int i = i0; i < n4; i += DEG_BLKS * 256) {
            int4 v = ((const int4*)ei)[i];
            atomicAdd(&g_deg[v.x], 1);
            atomicAdd(&g_deg[v.y], 1);
            atomicAdd(&g_deg[v.z], 1);
            atomicAdd(&g_deg[v.w], 1);
        }
        if (i0 < (E & 3)) atomicAdd(&g_deg[ei[n4 * 4 + i0]], 1);
    } else if (blockIdx.x < DEG_BLKS + GRAM_BLKS) {
        // ---- Gram: transposed padded tile, LDS.128 inner loop ----
        __shared__ float sh[RK * TP];
        int a = threadIdx.x >> 4, b = threadIdx.x & 15;
        int gb = blockIdx.x - DEG_BLKS;
        float acc = 0.0f;
        for (int row0 = gb * 128; row0 < N; row0 += GRAM_BLKS * 128) {
            __syncthreads();
            for (int t = threadIdx.x; t < 512; t += 256) {
                int row = t >> 2;
                int cb = (t & 3) * 4;
                int grow = row0 + row;
                float4 v = make_float4(0.f, 0.f, 0.f, 0.f);
                if (grow < N) v = ((const float4*)zs)[(size_t)grow * 4 + (t & 3)];
                sh[(cb + 0) * TP + row] = v.x;
                sh[(cb + 1) * TP + row] = v.y;
                sh[(cb + 2) * TP + row] = v.z;
                sh[(cb + 3) * TP + row] = v.w;
            }
            __syncthreads();
            const float4* ca = (const float4*)(sh + a * TP);
            const float4* cb4 = (const float4*)(sh + b * TP);
#pragma unroll 8
            for (int i = 0; i < 32; i++) {
                float4 va = ca[i];
                float4 vb = cb4[i];
                acc += va.x * vb.x + va.y * vb.y + va.z * vb.z + va.w * vb.w;
            }
        }
        atomicAdd(&g_gram[threadIdx.x], acc);
    } else {
        // ---- pack int4 rows (32B/node) + sum(z_mean^2); no deg dependency ----
        int sub = threadIdx.x & 7;
        int row = (blockIdx.x - DEG_BLKS - GRAM_BLKS) * 32 + (threadIdx.x >> 3);

        float acc = 0.0f;
        int pm = 0, ps = 0, word = 0;
        if (row < N) {
            if (sub < 4) {
                const float4* mr = (const float4*)(zm + (size_t)row * DM);
                float4 a = mr[2 * sub], b = mr[2 * sub + 1];
                acc = a.x * a.x + a.y * a.y + a.z * a.z + a.w * a.w
                    + b.x * b.x + b.y * b.y + b.z * b.z + b.w * b.w;
                float v[8] = {a.x, a.y, a.z, a.w, b.x, b.y, b.z, b.w};
                int n[8];
#pragma unroll
                for (int k = 0; k < 8; k++) { n[k] = q4n(v[k], MSQ4); pm += n[k]; }
#pragma unroll
                for (int k = 0; k < 4; k++)
                    word |= (n[2 * k] | (n[2 * k + 1] << 4)) << (8 * k);
            } else if (sub < 6) {
                const float4* sr = (const float4*)(zs + (size_t)row * RK);
                float4 a = sr[2 * (sub - 4)], b = sr[2 * (sub - 4) + 1];
                float v[8] = {a.x, a.y, a.z, a.w, b.x, b.y, b.z, b.w};
                int n[8];
#pragma unroll
                for (int k = 0; k < 8; k++) { n[k] = q4n(v[k], QS4S); ps += n[k]; }
#pragma unroll
                for (int k = 0; k < 4; k++)
                    word |= (n[2 * k] | (n[2 * k + 1] << 4)) << (8 * k);
            }
        }
        // reduce nibble sums over the aligned 8-lane group
        for (int o = 1; o < 8; o <<= 1) {
            pm += __shfl_xor_sync(0xffffffffu, pm, o);
            ps += __shfl_xor_sync(0xffffffffu, ps, o);
        }
        if (row < N) {
            if (sub == 7) word = (pm & 0xFFFF) | (ps << 16);
            g_pack[(size_t)row * PKW + sub] = word;
        }
        // sumsq block reduce
        for (int o = 16; o; o >>= 1) acc += __shfl_xor_sync(0xffffffffu, acc, o);
        __shared__ float shr[8];
        int w = threadIdx.x >> 5, l = threadIdx.x & 31;
        if (l == 0) shr[w] = acc;
        __syncthreads();
        if (threadIdx.x == 0) {
            float s = 0.0f;
            for (int i = 0; i < 8; i++) s += shr[i];
            atomicAdd(&g_acc[0], (double)s);
        }
    }
}

// Kernel 2: block 0 = shuffle-register Cholesky of I+Gram (then zero g_gram);
// blocks 1..: di = rsqrt(deg) into row word 6, zero g_deg.
__global__ void __launch_bounds__(256) k_patch(int N) {
    if (blockIdx.x == 0) {
        int tid = threadIdx.x;
        if (tid < 32) {
            int i = tid;
            float m[RK];
            float tr = 0.0f;
#pragma unroll
            for (int j = 0; j < RK; j++) {
                float g = (i < RK) ? g_gram[i * RK + j] : 0.0f;
                m[j] = g + (i == j ? 1.0f : 0.0f);
                if (i == j) tr = g;
            }
            for (int o = 8; o; o >>= 1) tr += __shfl_xor_sync(0xffffffffu, tr, o);

            float logdet = 0.0f;
#pragma unroll
            for (int k = 0; k < RK; k++) {
                float d = __shfl_sync(0xffffffffu, m[k], k);
                logdet += __logf(d);
                float rinv = rsqrtf(d);
                if (i >= k) m[k] *= rinv;
#pragma unroll
                for (int j = k + 1; j < RK; j++) {
                    float ljk = __shfl_sync(0xffffffffu, m[k], j);
                    if (i >= j) m[j] -= m[k] * ljk;
                }
            }
            if (tid == 0) {
                g_misc[0] = logdet;
                g_misc[1] = tr;
            }
        }
        __syncthreads();
        if (threadIdx.x < RK * RK) g_gram[threadIdx.x] = 0.0f;
    } else {
        int node = (blockIdx.x - 1) * 256 + threadIdx.x;
        if (node < N) {
            int d = g_deg[node];
            float di = (d > 0) ? rsqrtf((float)d) : 0.0f;
            ((float*)g_pack)[(size_t)node * PKW + 6] = di;
            g_deg[node] = 0;                   // reset for next replay
        }
    }
}

// ---------------------------------------------------------------------------
__device__ __forceinline__ void finalize_if_last(float* out, int N) {
    __threadfence();
    if (threadIdx.x == 0) {
        unsigned v = atomicAdd(&g_done, 1u);
        if (v == EDGE_BLKS - 1) {
            double logdet = (double)g_misc[0];
            double tr = (double)g_misc[1];
            double trace_L = (double)N - g_acc[2];
            double res = (g_acc[0] / (double)DM + tr + trace_L - g_acc[1]
                          - logdet) / (2.0 * (double)N);
            out[0] = (float)res;
            g_acc[0] = 0.0; g_acc[1] = 0.0; g_acc[2] = 0.0;
            g_misc[0] = 0.0f; g_misc[1] = 0.0f;
            g_done = 0u;
        }
    }
}

// dot of 8 biased-nibble pairs in two int32 (signed dp4a on 0..15 bytes)
__device__ __forceinline__ int nibdot(int a, int b) {
    const int M = 0x0F0F0F0F;
    int s = __dp4a(a & M, b & M, 0);
    return __dp4a((a >> 4) & M, (b >> 4) & M, s);
}

// Per-edge body: 2 lanes/edge, 16B each (rows are 32B = 1 sector).
// Lane 0: biased mean nibble dot. Lane 1: std dot + di weight + bias
// corrections (using precomputed per-row nibble sums in word 7).
// act=0 disables the edge (loads clamped to row 0, weight zeroed).
__device__ __forceinline__ void edge_body(int r, int c, int sub, int lane,
                                          bool act, float& accF, float& aself) {
    int4 ua = __ldg((const int4*)(g_pack + (size_t)r * PKW) + sub);
    int4 ub = __ldg((const int4*)(g_pack + (size_t)c * PKW) + sub);
    float fw = 0.0f;
    float contrib;
    if (sub == 0) {
        int bm = nibdot(ua.x, ub.x) + nibdot(ua.y, ub.y)
               + nibdot(ua.z, ub.z) + nibdot(ua.w, ub.w);
        contrib = (float)bm;               // scaled by CM4 at the end
    } else {
        int bs = nibdot(ua.x, ub.x) + nibdot(ua.y, ub.y);
        float dr = __int_as_float(ua.z);
        float dc = __int_as_float(ub.z);
        if (act) {
            fw = dr * dc;
            if (r == c) aself += dr * dr;
        }
        int SmA = ua.w & 0xFFFF, SmB = ub.w & 0xFFFF;
        int SsA = (int)((unsigned)ua.w >> 16), SsB = (int)((unsigned)ub.w >> 16);
        contrib = CM4 * (float)(2048 - 8 * (SmA + SmB))
                + CS4 * (float)(bs - 8 * (SsA + SsB) + 1024);
    }
    fw = __shfl_sync(0xffffffffu, fw, lane | 1);
    accF = fmaf(fw, contrib, accF);
}

// Kernel 3: edges (EDGE_BLKS blocks) + last-block finalize.
__global__ void __launch_bounds__(256) k_edges(
    const int* __restrict__ ei, int E, float* out, int N) {
    int tid = blockIdx.x * blockDim.x + threadIdx.x;
    int sub = threadIdx.x & 1;
    int lane = threadIdx.x & 31;
    int gid = tid >> 1;
    int gstride = (EDGE_BLKS * 256) >> 1;

    float acc0 = 0.f, acc1 = 0.f, acc2 = 0.f, acc3 = 0.f;
    float aself = 0.0f;

    int iters = (E + gstride - 1) / gstride;
    int U = iters - 1;                 // unguarded iterations
    int it = 0;
    for (; it + 3 < U; it += 4) {
        int e0 = gid + it * gstride;
        int e1 = e0 + gstride, e2 = e1 + gstride, e3 = e2 + gstride;
        int r0 = __ldg(ei + e0), c0 = __ldg(ei + (size_t)E + e0);
        int r1 = __ldg(ei + e1), c1 = __ldg(ei + (size_t)E + e1);
        int r2 = __ldg(ei + e2), c2 = __ldg(ei + (size_t)E + e2);
        int r3 = __ldg(ei + e3), c3 = __ldg(ei + (size_t)E + e3);
        edge_body(r0, c0, sub, lane, true, acc0, aself);
        edge_body(r1, c1, sub, lane, true, acc1, aself);
        edge_body(r2, c2, sub, lane, true, acc2, aself);
        edge_body(r3, c3, sub, lane, true, acc3, aself);
    }
    for (; it < U; it++) {
        int e = gid + it * gstride;
        int r = __ldg(ei + e), c = __ldg(ei + (size_t)E + e);
        edge_body(r, c, sub, lane, true, acc0, aself);
    }
    {   // tail: executed by ALL threads (shfl-safe); inactive edges zeroed
        int e = gid + U * gstride;
        bool act = (e < E);
        int es = act ? e : 0;
        int r = __ldg(ei + es), c = __ldg(ei + (size_t)E + es);
        edge_body(r, c, sub, lane, act, acc1, aself);
    }

    // lane scale: lane 0 carries raw mean dot (CM4); lane 1 already scaled
    float lscale = (sub == 0) ? CM4 : 1.0f;
    float accD = ((acc0 + acc1) + (acc2 + acc3)) * lscale;

    // block reduce
    for (int o = 16; o; o >>= 1) {
        accD += __shfl_xor_sync(0xffffffffu, accD, o);
        aself += __shfl_xor_sync(0xffffffffu, aself, o);
    }
    __shared__ float s0[8], s1[8];
    int w = threadIdx.x >> 5, l = threadIdx.x & 31;
    if (l == 0) { s0[w] = accD; s1[w] = aself; }
    __syncthreads();
    if (threadIdx.x == 0) {
        float A = 0.f, B = 0.f;
        for (int i = 0; i < 8; i++) { A += s0[i]; B += s1[i]; }
        atomicAdd(&g_acc[1], (double)A);
        atomicAdd(&g_acc[2], (double)B);
    }
    finalize_if_last(out, N);
}

// ---------------------------------------------------------------------------
extern "C" void kernel_launch(void* const* d_in, const int* in_sizes, int n_in,
                              void* d_out, int out_size) {
    const float* zm = (const float*)d_in[0];
    const float* zs = (const float*)d_in[1];
    const int*   ei = (const int*)d_in[2];

    int N = in_sizes[0] / DM;
    int E = in_sizes[2] / 2;

    k_prep<<<DEG_BLKS + GRAM_BLKS + PACK_BLKS, 256>>>(zm, zs, ei, N, E);
    k_patch<<<1 + (N + 255) / 256, 256>>>(N);
    k_edges<<<EDGE_BLKS, 256>>>(ei, E, (float*)d_out, N);
}

// round 17
// speedup vs baseline: 1.7576x; 1.0029x over previous
#include <cuda_runtime.h>
#include <math.h>

#define MAXN 100000
#define DM 32
#define RK 16
#define PKW 8          // row: 8 int32 = 32 B (4w mean nib, 2w std nib, 1w di, 1w sums)
#define QS4M 11.0f     // int4 mean quant scale (applied to zm/sqrt(32))
#define QS4S 2.0f      // int4 std quant scale
#define MSQ4 (0.17677669529663687f * QS4M)
#define CM4  (1.0f / (QS4M * QS4M))
#define CS4  (1.0f / (QS4S * QS4S))
#define DEG_BLKS 592
#define GRAM_BLKS 296
#define PACK_BLKS 3125
#define TP 132         // padded transposed tile stride
#define EDGE_BLKS 888

// Scratch. Invariant: g_deg/g_acc/g_gram/g_misc/g_done are ZERO at entry
// (zero-init at load; re-zeroed inside the pipeline every run).
__device__ int    g_deg[MAXN];
__device__ double g_acc[3];          // 0: sum(z_mean^2), 1: D, 2: selfloop w sum
__device__ float  g_gram[RK * RK];   // z_std^T z_std (float atomics)
__device__ float  g_misc[2];         // 0: logdet, 1: trace(Gram)
__device__ unsigned g_done;          // completion counter for last-block finalize
__device__ __align__(32) int g_pack[MAXN * PKW];  // 3.2 MB nibble rows

// ---------------------------------------------------------------------------
__device__ __forceinline__ int q4n(float v, float s) {   // biased nibble 1..15
    int q = __float2int_rn(v * s);
    return max(-7, min(7, q)) + 8;
}

// Kernel 1: three independent jobs in one launch (deg ∥ gram ∥ pack).
// (256,8): force <=32 regs -> 8 CTAs/SM; the kernel is issue/latency bound.
__global__ void __launch_bounds__(256, 8) k_prep(
    const float* __restrict__ zm, const float* __restrict__ zs,
    const int* __restrict__ ei, int N, int E) {
    if (blockIdx.x < DEG_BLKS) {
        // ---- degree histogram (int4-vectorized atomics over row half) ----
        int i0 = blockIdx.x * blockDim.x + threadIdx.x;
        int n4 = E >> 2;
        for (int i = i0; i < n4; i += DEG_BLKS * 256) {
            int4 v = ((const int4*)ei)[i];
            atomicAdd(&g_deg[v.x], 1);
            atomicAdd(&g_deg[v.y], 1);
            atomicAdd(&g_deg[v.z], 1);
            atomicAdd(&g_deg[v.w], 1);
        }
        if (i0 < (E & 3)) atomicAdd(&g_deg[ei[n4 * 4 + i0]], 1);
    } else if (blockIdx.x < DEG_BLKS + GRAM_BLKS) {
        // ---- Gram: transposed padded tile, LDS.128 inner loop ----
        __shared__ float sh[RK * TP];
        int a = threadIdx.x >> 4, b = threadIdx.x & 15;
        int gb = blockIdx.x - DEG_BLKS;
        float acc = 0.0f;
        for (int row0 = gb * 128; row0 < N; row0 += GRAM_BLKS * 128) {
            __syncthreads();
            for (int t = threadIdx.x; t < 512; t += 256) {
                int row = t >> 2;
                int cb = (t & 3) * 4;
                int grow = row0 + row;
                float4 v = make_float4(0.f, 0.f, 0.f, 0.f);
                if (grow < N) v = ((const float4*)zs)[(size_t)grow * 4 + (t & 3)];
                sh[(cb + 0) * TP + row] = v.x;
                sh[(cb + 1) * TP + row] = v.y;
                sh[(cb + 2) * TP + row] = v.z;
                sh[(cb + 3) * TP + row] = v.w;
            }
            __syncthreads();
            const float4* ca = (const float4*)(sh + a * TP);
            const float4* cb4 = (const float4*)(sh + b * TP);
#pragma unroll 8
            for (int i = 0; i < 32; i++) {
                float4 va = ca[i];
                float4 vb = cb4[i];
                acc += va.x * vb.x + va.y * vb.y + va.z * vb.z + va.w * vb.w;
            }
        }
        atomicAdd(&g_gram[threadIdx.x], acc);
    } else {
        // ---- pack int4 rows (32B/node) + sum(z_mean^2); no deg dependency ----
        int sub = threadIdx.x & 7;
        int row = (blockIdx.x - DEG_BLKS - GRAM_BLKS) * 32 + (threadIdx.x >> 3);

        float acc = 0.0f;
        int pm = 0, ps = 0, word = 0;
        if (row < N) {
            if (sub < 4) {
                const float4* mr = (const float4*)(zm + (size_t)row * DM);
                float4 a = mr[2 * sub], b = mr[2 * sub + 1];
                acc = a.x * a.x + a.y * a.y + a.z * a.z + a.w * a.w
                    + b.x * b.x + b.y * b.y + b.z * b.z + b.w * b.w;
                float v[8] = {a.x, a.y, a.z, a.w, b.x, b.y, b.z, b.w};
                int n[8];
#pragma unroll
                for (int k = 0; k < 8; k++) { n[k] = q4n(v[k], MSQ4); pm += n[k]; }
#pragma unroll
                for (int k = 0; k < 4; k++)
                    word |= (n[2 * k] | (n[2 * k + 1] << 4)) << (8 * k);
            } else if (sub < 6) {
                const float4* sr = (const float4*)(zs + (size_t)row * RK);
                float4 a = sr[2 * (sub - 4)], b = sr[2 * (sub - 4) + 1];
                float v[8] = {a.x, a.y, a.z, a.w, b.x, b.y, b.z, b.w};
                int n[8];
#pragma unroll
                for (int k = 0; k < 8; k++) { n[k] = q4n(v[k], QS4S); ps += n[k]; }
#pragma unroll
                for (int k = 0; k < 4; k++)
                    word |= (n[2 * k] | (n[2 * k + 1] << 4)) << (8 * k);
            }
        }
        // reduce nibble sums over the aligned 8-lane group
        for (int o = 1; o < 8; o <<= 1) {
            pm += __shfl_xor_sync(0xffffffffu, pm, o);
            ps += __shfl_xor_sync(0xffffffffu, ps, o);
        }
        if (row < N) {
            if (sub == 7) word = (pm & 0xFFFF) | (ps << 16);
            g_pack[(size_t)row * PKW + sub] = word;
        }
        // sumsq block reduce
        for (int o = 16; o; o >>= 1) acc += __shfl_xor_sync(0xffffffffu, acc, o);
        __shared__ float shr[8];
        int w = threadIdx.x >> 5, l = threadIdx.x & 31;
        if (l == 0) shr[w] = acc;
        __syncthreads();
        if (threadIdx.x == 0) {
            float s = 0.0f;
            for (int i = 0; i < 8; i++) s += shr[i];
            atomicAdd(&g_acc[0], (double)s);
        }
    }
}

// Kernel 2: block 0 = shuffle-register Cholesky of I+Gram (then zero g_gram);
// blocks 1..: di = rsqrt(deg) into row word 6, zero g_deg.
__global__ void __launch_bounds__(256) k_patch(int N) {
    if (blockIdx.x == 0) {
        int tid = threadIdx.x;
        if (tid < 32) {
            int i = tid;
            float m[RK];
            float tr = 0.0f;
#pragma unroll
            for (int j = 0; j < RK; j++) {
                float g = (i < RK) ? g_gram[i * RK + j] : 0.0f;
                m[j] = g + (i == j ? 1.0f : 0.0f);
                if (i == j) tr = g;
            }
            for (int o = 8; o; o >>= 1) tr += __shfl_xor_sync(0xffffffffu, tr, o);

            float logdet = 0.0f;
#pragma unroll
            for (int k = 0; k < RK; k++) {
                float d = __shfl_sync(0xffffffffu, m[k], k);
                logdet += __logf(d);
                float rinv = rsqrtf(d);
                if (i >= k) m[k] *= rinv;
#pragma unroll
                for (int j = k + 1; j < RK; j++) {
                    float ljk = __shfl_sync(0xffffffffu, m[k], j);
                    if (i >= j) m[j] -= m[k] * ljk;
                }
            }
            if (tid == 0) {
                g_misc[0] = logdet;
                g_misc[1] = tr;
            }
        }
        __syncthreads();
        if (threadIdx.x < RK * RK) g_gram[threadIdx.x] = 0.0f;
    } else {
        int node = (blockIdx.x - 1) * 256 + threadIdx.x;
        if (node < N) {
            int d = g_deg[node];
            float di = (d > 0) ? rsqrtf((float)d) : 0.0f;
            ((float*)g_pack)[(size_t)node * PKW + 6] = di;
            g_deg[node] = 0;                   // reset for next replay
        }
    }
}

// ---------------------------------------------------------------------------
__device__ __forceinline__ void finalize_if_last(float* out, int N) {
    __threadfence();
    if (threadIdx.x == 0) {
        unsigned v = atomicAdd(&g_done, 1u);
        if (v == EDGE_BLKS - 1) {
            double logdet = (double)g_misc[0];
            double tr = (double)g_misc[1];
            double trace_L = (double)N - g_acc[2];
            double res = (g_acc[0] / (double)DM + tr + trace_L - g_acc[1]
                          - logdet) / (2.0 * (double)N);
            out[0] = (float)res;
            g_acc[0] = 0.0; g_acc[1] = 0.0; g_acc[2] = 0.0;
            g_misc[0] = 0.0f; g_misc[1] = 0.0f;
            g_done = 0u;
        }
    }
}

// dot of 8 biased-nibble pairs in two int32 (signed dp4a on 0..15 bytes)
__device__ __forceinline__ int nibdot(int a, int b) {
    const int M = 0x0F0F0F0F;
    int s = __dp4a(a & M, b & M, 0);
    return __dp4a((a >> 4) & M, (b >> 4) & M, s);
}

// Per-edge body: 2 lanes/edge, 16B each (rows are 32B = 1 sector).
__device__ __forceinline__ void edge_body(int r, int c, int sub, int lane,
                                          bool act, float& accF, float& aself) {
    int4 ua = __ldg((const int4*)(g_pack + (size_t)r * PKW) + sub);
    int4 ub = __ldg((const int4*)(g_pack + (size_t)c * PKW) + sub);
    float fw = 0.0f;
    float contrib;
    if (sub == 0) {
        int bm = nibdot(ua.x, ub.x) + nibdot(ua.y, ub.y)
               + nibdot(ua.z, ub.z) + nibdot(ua.w, ub.w);
        contrib = (float)bm;               // scaled by CM4 at the end
    } else {
        int bs = nibdot(ua.x, ub.x) + nibdot(ua.y, ub.y);
        float dr = __int_as_float(ua.z);
        float dc = __int_as_float(ub.z);
        if (act) {
            fw = dr * dc;
            if (r == c) aself += dr * dr;
        }
        int SmA = ua.w & 0xFFFF, SmB = ub.w & 0xFFFF;
        int SsA = (int)((unsigned)ua.w >> 16), SsB = (int)((unsigned)ub.w >> 16);
        contrib = CM4 * (float)(2048 - 8 * (SmA + SmB))
                + CS4 * (float)(bs - 8 * (SsA + SsB) + 1024);
    }
    fw = __shfl_sync(0xffffffffu, fw, lane | 1);
    accF = fmaf(fw, contrib, accF);
}

// Kernel 3: edges (EDGE_BLKS blocks, exactly 6/SM resident) + last-block finalize.
__global__ void __launch_bounds__(256, 6) k_edges(
    const int* __restrict__ ei, int E, float* out, int N) {
    int tid = blockIdx.x * blockDim.x + threadIdx.x;
    int sub = threadIdx.x & 1;
    int lane = threadIdx.x & 31;
    int gid = tid >> 1;
    int gstride = (EDGE_BLKS * 256) >> 1;

    float acc0 = 0.f, acc1 = 0.f, acc2 = 0.f, acc3 = 0.f;
    float aself = 0.0f;

    int iters = (E + gstride - 1) / gstride;
    int U = iters - 1;                 // unguarded iterations
    int it = 0;
    for (; it + 3 < U; it += 4) {
        int e0 = gid + it * gstride;
        int e1 = e0 + gstride, e2 = e1 + gstride, e3 = e2 + gstride;
        int r0 = __ldg(ei + e0), c0 = __ldg(ei + (size_t)E + e0);
        int r1 = __ldg(ei + e1), c1 = __ldg(ei + (size_t)E + e1);
        int r2 = __ldg(ei + e2), c2 = __ldg(ei + (size_t)E + e2);
        int r3 = __ldg(ei + e3), c3 = __ldg(ei + (size_t)E + e3);
        edge_body(r0, c0, sub, lane, true, acc0, aself);
        edge_body(r1, c1, sub, lane, true, acc1, aself);
        edge_body(r2, c2, sub, lane, true, acc2, aself);
        edge_body(r3, c3, sub, lane, true, acc3, aself);
    }
    for (; it < U; it++) {
        int e = gid + it * gstride;
        int r = __ldg(ei + e), c = __ldg(ei + (size_t)E + e);
        edge_body(r, c, sub, lane, true, acc0, aself);
    }
    {   // tail: executed by ALL threads (shfl-safe); inactive edges zeroed
        int e = gid + U * gstride;
        bool act = (e < E);
        int es = act ? e : 0;
        int r = __ldg(ei + es), c = __ldg(ei + (size_t)E + es);
        edge_body(r, c, sub, lane, act, acc1, aself);
    }

    // lane scale: lane 0 carries raw mean dot (CM4); lane 1 already scaled
    float lscale = (sub == 0) ? CM4 : 1.0f;
    float accD = ((acc0 + acc1) + (acc2 + acc3)) * lscale;

    // block reduce
    for (int o = 16; o; o >>= 1) {
        accD += __shfl_xor_sync(0xffffffffu, accD, o);
        aself += __shfl_xor_sync(0xffffffffu, aself, o);
    }
    __shared__ float s0[8], s1[8];
    int w = threadIdx.x >> 5, l = threadIdx.x & 31;
    if (l == 0) { s0[w] = accD; s1[w] = aself; }
    __syncthreads();
    if (threadIdx.x == 0) {
        float A = 0.f, B = 0.f;
        for (int i = 0; i < 8; i++) { A += s0[i]; B += s1[i]; }
        atomicAdd(&g_acc[1], (double)A);
        atomicAdd(&g_acc[2], (double)B);
    }
    finalize_if_last(out, N);
}

// ---------------------------------------------------------------------------
extern "C" void kernel_launch(void* const* d_in, const int* in_sizes, int n_in,
                              void* d_out, int out_size) {
    const float* zm = (const float*)d_in[0];
    const float* zs = (const float*)d_in[1];
    const int*   ei = (const int*)d_in[2];

    int N = in_sizes[0] / DM;
    int E = in_sizes[2] / 2;

    k_prep<<<DEG_BLKS + GRAM_BLKS + PACK_BLKS, 256>>>(zm, zs, ei, N, E);
    k_patch<<<1 + (N + 255) / 256, 256>>>(N);
    k_edges<<<EDGE_BLKS, 256>>>(ei, E, (float*)d_out, N);
}